// round 13
// baseline (speedup 1.0000x reference)
#include <cuda_runtime.h>

// 3-level Haar DWT, fully fused, persistent grid-stride (single wave).
// x: [B, L=16384] fp32. Output concat: [cA3 (B*2048) | cD3 (B*2048) | cD2 (B*4096) | cD1 (B*8192)]
//
// R10's proven memory pattern (8 inputs/thread, 2x LDG.128, default cache policy,
// coalesced vector stores) inside a grid-stride loop sized to exactly one wave
// (SMs * 8 CTAs of 256 threads) to eliminate ~13 wave transitions + ragged tail.

__global__ __launch_bounds__(256) void haar3_persistent(
    const float4* __restrict__ in4,   // input viewed as float4
    float*  __restrict__ cA3,         // B*2048
    float*  __restrict__ cD3,         // B*2048
    float2* __restrict__ cD2_2,       // B*4096 floats = B*2048 float2
    float4* __restrict__ cD1_4,       // B*8192 floats = B*2048 float4
    int total_groups)                 // B * 2048
{
    const float S  = 0.70710678118654752440f;   // sqrt(1/2)
    const float S2 = 0.5f;                      // S^2
    const float S3 = 0.35355339059327376220f;   // S^3

    int stride = gridDim.x * blockDim.x;

    for (int t = blockIdx.x * blockDim.x + threadIdx.x; t < total_groups; t += stride) {
        float4 v0 = in4[2 * t];
        float4 v1 = in4[2 * t + 1];

        // level 1 pair sums/diffs
        float a0 = v0.x + v0.y, d0 = v0.x - v0.y;
        float a1 = v0.z + v0.w, d1 = v0.z - v0.w;
        float a2 = v1.x + v1.y, d2 = v1.x - v1.y;
        float a3 = v1.z + v1.w, d3 = v1.z - v1.w;

        // level 2
        float A0 = a0 + a1, D0 = a0 - a1;
        float A1 = a2 + a3, D1 = a2 - a3;

        // level 3
        float ca3 = S3 * (A0 + A1);
        float cd3 = S3 * (A0 - A1);

        // stores — default caching, all coalesced
        cD1_4[t] = make_float4(S * d0, S * d1, S * d2, S * d3);
        cD2_2[t] = make_float2(S2 * D0, S2 * D1);
        cD3[t]   = cd3;
        cA3[t]   = ca3;
    }
}

extern "C" void kernel_launch(void* const* d_in, const int* in_sizes, int n_in,
                              void* d_out, int out_size)
{
    const float* x = (const float*)d_in[0];
    float* out = (float*)d_out;

    const int L = 16384;
    const int B = in_sizes[0] / L;          // 2048
    const int total_groups = B * (L / 8);   // B * 2048

    // Output layout: [cA3 | cD3 | cD2 | cD1]
    float*  cA3  = out;
    float*  cD3  = out + (size_t)B * (L / 8);                 // + B*2048
    float2* cD2  = (float2*)(out + (size_t)2 * B * (L / 8));  // + B*4096 floats
    float4* cD1  = (float4*)(out + (size_t)B * (L / 2));      // + B*8192 floats

    // One wave: SMs * 8 CTAs (256 thr, <=32 regs -> 2048 thr/SM)
    int sms = 148;
    cudaDeviceGetAttribute(&sms, cudaDevAttrMultiProcessorCount, 0);
    int threads = 256;
    int blocks_needed = (total_groups + threads - 1) / threads;
    int blocks = sms * 8;
    if (blocks > blocks_needed) blocks = blocks_needed;

    haar3_persistent<<<blocks, threads>>>((const float4*)x, cA3, cD3, cD2, cD1, total_groups);
}

// round 14
// speedup vs baseline: 1.0941x; 1.0941x over previous
#include <cuda_runtime.h>
#include <cstdint>

// 3-level Haar DWT, fully fused, 16 inputs/thread with Blackwell 256-bit ld/st.
// x: [B, L=16384] fp32. Output concat: [cA3 (B*2048) | cD3 (B*2048) | cD2 (B*4096) | cD1 (B*8192)]
//
// Per thread (t = 0 .. B*1024-1), inputs [16t, 16t+16):
//   loads : 2x ld.global.v8.f32  (64B contiguous, 32B-aligned)
//   stores: cD1 1x st.global.v8.f32, cD2 STG.128, cD3/cA3 STG.64 — all coalesced.
// Default cache policy everywhere (hints measured harmful in R11/R12).

__global__ __launch_bounds__(256) void haar3_v8(
    const float* __restrict__ in,     // B*16384
    float2* __restrict__ cA3_2,       // B*2048 floats
    float2* __restrict__ cD3_2,       // B*2048 floats
    float4* __restrict__ cD2_4,       // B*4096 floats
    float*  __restrict__ cD1,         // B*8192 floats
    int total)                        // B * 1024
{
    int t = blockIdx.x * blockDim.x + threadIdx.x;
    if (t >= total) return;

    const float S  = 0.70710678118654752440f;   // 2^-1/2
    const float S2 = 0.5f;
    const float S3 = 0.35355339059327376220f;   // 2^-3/2

    const float* p = in + (size_t)t * 16;

    float x0,x1,x2,x3,x4,x5,x6,x7,x8,x9,x10,x11,x12,x13,x14,x15;
    asm volatile("ld.global.v8.f32 {%0,%1,%2,%3,%4,%5,%6,%7}, [%8];"
        : "=f"(x0),"=f"(x1),"=f"(x2),"=f"(x3),
          "=f"(x4),"=f"(x5),"=f"(x6),"=f"(x7)
        : "l"(p));
    asm volatile("ld.global.v8.f32 {%0,%1,%2,%3,%4,%5,%6,%7}, [%8];"
        : "=f"(x8),"=f"(x9),"=f"(x10),"=f"(x11),
          "=f"(x12),"=f"(x13),"=f"(x14),"=f"(x15)
        : "l"(p + 8));

    // ---- level 1: 8 pair sums / diffs ----
    float a0 = x0  + x1,  d0 = x0  - x1;
    float a1 = x2  + x3,  d1 = x2  - x3;
    float a2 = x4  + x5,  d2 = x4  - x5;
    float a3 = x6  + x7,  d3 = x6  - x7;
    float a4 = x8  + x9,  d4 = x8  - x9;
    float a5 = x10 + x11, d5 = x10 - x11;
    float a6 = x12 + x13, d6 = x12 - x13;
    float a7 = x14 + x15, d7 = x14 - x15;

    // ---- level 2 ----
    float A0 = a0 + a1, D0 = a0 - a1;
    float A1 = a2 + a3, D1 = a2 - a3;
    float A2 = a4 + a5, D2 = a4 - a5;
    float A3 = a6 + a7, D3 = a6 - a7;

    // ---- level 3 ----
    float ca0 = S3 * (A0 + A1), cd0 = S3 * (A0 - A1);
    float ca1 = S3 * (A2 + A3), cd1 = S3 * (A2 - A3);

    // ---- stores ----
    float* q = cD1 + (size_t)t * 8;
    asm volatile("st.global.v8.f32 [%8], {%0,%1,%2,%3,%4,%5,%6,%7};"
        :: "f"(S*d0),"f"(S*d1),"f"(S*d2),"f"(S*d3),
           "f"(S*d4),"f"(S*d5),"f"(S*d6),"f"(S*d7),
           "l"(q) : "memory");

    cD2_4[t] = make_float4(S2 * D0, S2 * D1, S2 * D2, S2 * D3);
    cD3_2[t] = make_float2(cd0, cd1);
    cA3_2[t] = make_float2(ca0, ca1);
}

extern "C" void kernel_launch(void* const* d_in, const int* in_sizes, int n_in,
                              void* d_out, int out_size)
{
    const float* x = (const float*)d_in[0];
    float* out = (float*)d_out;

    const int L = 16384;
    const int B = in_sizes[0] / L;      // 2048
    const int total = B * (L / 16);     // B * 1024

    // Output layout: [cA3 | cD3 | cD2 | cD1]
    float2* cA3 = (float2*)out;
    float2* cD3 = (float2*)(out + (size_t)B * (L / 8));      // + B*2048
    float4* cD2 = (float4*)(out + (size_t)2 * B * (L / 8));  // + B*4096
    float*  cD1 = out + (size_t)B * (L / 2);                 // + B*8192

    int threads = 256;
    int blocks = (total + threads - 1) / threads;
    haar3_v8<<<blocks, threads>>>(x, cA3, cD3, cD2, cD1, total);
}